// round 17
// baseline (speedup 1.0000x reference)
#include <cuda_runtime.h>
#include <cuda_bf16.h>
#include <cuda_fp16.h>
#include <cstdint>

#define BATCH 8
#define SEQ   2048
#define DM    1024
#define DH    64
#define NTOK  (BATCH * SEQ)
#define ITILES 16

// ---------------- device scratch ----------------
__device__ __half g_W[3 * DH * DM];                // [mat*64+c][k], fp16
__device__ __half g_Q[NTOK * DH];                  // Q fp16
__device__ __half g_K[NTOK * DH];                  // K fp16
__device__ __half g_E[(size_t)NTOK * SEQ];         // exp(S) fp16, [b,i,j]
__device__ __half g_Vf[BATCH * DH * SEQ];          // V fp16 UNSCALED, [b][d][i]
__device__ float  g_csum[BATCH * SEQ];             // atomic column sums

// ---------------- helpers ----------------
__device__ __forceinline__ uint32_t s_u32(const void* p) {
    uint32_t a;
    asm("{ .reg .u64 t; cvta.to.shared.u64 t, %1; cvt.u32.u64 %0, t; }" : "=r"(a) : "l"(p));
    return a;
}
#define LDSM4(r0, r1, r2, r3, addr) \
    asm volatile("ldmatrix.sync.aligned.m8n8.x4.shared.b16 {%0,%1,%2,%3}, [%4];" \
                 : "=r"(r0), "=r"(r1), "=r"(r2), "=r"(r3) : "r"(addr))
#define CPA16(dst, src) \
    asm volatile("cp.async.cg.shared.global [%0], [%1], 16;" :: "r"(dst), "l"(src))
#define CPA_COMMIT() asm volatile("cp.async.commit_group;" ::: "memory")
#define CPA_WAIT1()  asm volatile("cp.async.wait_group 1;" ::: "memory")
#define CPA_WAIT0()  asm volatile("cp.async.wait_group 0;" ::: "memory")

__device__ __forceinline__ void mma_f16(float* c, const uint32_t* a, const uint32_t* b) {
    asm volatile(
        "mma.sync.aligned.m16n8k16.row.col.f32.f16.f16.f32 "
        "{%0,%1,%2,%3}, {%4,%5,%6,%7}, {%8,%9}, {%0,%1,%2,%3};"
        : "+f"(c[0]), "+f"(c[1]), "+f"(c[2]), "+f"(c[3])
        : "r"(a[0]), "r"(a[1]), "r"(a[2]), "r"(a[3]), "r"(b[0]), "r"(b[1]));
}
__device__ __forceinline__ uint32_t pk2(unsigned short a, unsigned short b) {
    return (uint32_t)a | ((uint32_t)b << 16);
}
__device__ __forceinline__ unsigned short h16(float v) {
    return __half_as_ushort(__float2half(v));
}

// ---------------- W -> fp16 transpose (+ zero g_csum) ----------------
__global__ __launch_bounds__(256) void split_w_kernel(
    const float* __restrict__ Wq, const float* __restrict__ Wk, const float* __restrict__ Wv) {
    int mt = blockIdx.y;
    const float* W = (mt == 0) ? Wq : (mt == 1) ? Wk : Wv;
    int idx = blockIdx.x * 256 + threadIdx.x;
    int k = idx >> 6, c = idx & 63;
    g_W[(mt * 64 + c) * DM + k] = __float2half(W[k * DH + c]);
    if (mt == 0 && idx < BATCH * SEQ) g_csum[idx] = 0.f;
}

// ---------------- fused QKV projection: 64-row tiles, 256 CTAs ----------------
// grid 256, block 256 (8 warps 2x4). Stage (36864 B x2): A[64][72] @0 (9216), B[192][72] @9216 (27648)
__global__ __launch_bounds__(256) void proj_kernel(
    const float* __restrict__ x, const float* __restrict__ bq,
    const float* __restrict__ bk, const float* __restrict__ bv) {
    extern __shared__ char smem[];
    const uint32_t sbase = s_u32(smem);
    const int tid = threadIdx.x, lane = tid & 31, w = tid >> 5;
    const int row0 = blockIdx.x * 64;
    const int bb = row0 >> 11, iloc = row0 & 2047;

    const int wm = w & 1, wn = w >> 1;          // rows wm*32, cols wn*48
    float acc[2][6][4];
    #pragma unroll
    for (int i = 0; i < 2; i++)
        #pragma unroll
        for (int j = 0; j < 6; j++)
            #pragma unroll
            for (int q = 0; q < 4; q++) acc[i][j][q] = 0.f;

    const int xr_r = tid >> 2, xr_c = (tid & 3) * 16;

    auto ldx = [&](int kc, float4* xr) {
        const float4* src = (const float4*)(x + (size_t)(row0 + xr_r) * DM + kc * 64 + xr_c);
        xr[0] = src[0]; xr[1] = src[1]; xr[2] = src[2]; xr[3] = src[3];
    };
    auto convA = [&](const float4* xr, int st) {
        __half* A = (__half*)(smem + st * 36864);
        unsigned short hs[16];
        #pragma unroll
        for (int q = 0; q < 4; q++) {
            float4 v = xr[q];
            hs[q*4+0] = h16(v.x); hs[q*4+1] = h16(v.y);
            hs[q*4+2] = h16(v.z); hs[q*4+3] = h16(v.w);
        }
        uint4* dh = (uint4*)(A + xr_r * 72 + xr_c);
        dh[0] = make_uint4(pk2(hs[0],hs[1]), pk2(hs[2],hs[3]), pk2(hs[4],hs[5]), pk2(hs[6],hs[7]));
        dh[1] = make_uint4(pk2(hs[8],hs[9]), pk2(hs[10],hs[11]), pk2(hs[12],hs[13]), pk2(hs[14],hs[15]));
    };
    auto ldW = [&](int kc, int st) {
        uint32_t bw = sbase + st * 36864 + 9216;
        #pragma unroll
        for (int p = 0; p < 6; p++) {
            int lin = p * 256 + tid, r = lin >> 3, q = lin & 7;
            CPA16(bw + (uint32_t)(r * 144 + q * 16),
                  (const char*)g_W + ((size_t)r * DM + kc * 64) * 2 + q * 16);
        }
        CPA_COMMIT();
    };

    float4 xr[4];
    ldx(0, xr);
    ldW(0, 0);
    convA(xr, 0);
    CPA_WAIT0();
    __syncthreads();

    for (int c = 0; c < 16; c++) {
        const int cur = c & 1;
        if (c < 15) { ldx(c + 1, xr); ldW(c + 1, cur ^ 1); }

        const uint32_t S = sbase + cur * 36864;
        const uint32_t sA = S, sB = S + 9216;
        #pragma unroll
        for (int ks = 0; ks < 4; ks++) {
            const int k0 = ks * 16;
            uint32_t a[2][4];
            #pragma unroll
            for (int mf = 0; mf < 2; mf++) {
                uint32_t off = (uint32_t)((wm * 32 + mf * 16 + (lane & 15)) * 72 +
                                          k0 + ((lane >> 4) << 3)) * 2;
                LDSM4(a[mf][0], a[mf][1], a[mf][2], a[mf][3], sA + off);
            }
            uint32_t b[6][2];
            #pragma unroll
            for (int nb = 0; nb < 3; nb++) {
                uint32_t off = (uint32_t)((wn * 48 + nb * 16 + (lane & 7) + ((lane >> 4) << 3)) * 72 +
                                          k0 + (((lane >> 3) & 1) << 3)) * 2;
                LDSM4(b[2*nb][0], b[2*nb][1], b[2*nb+1][0], b[2*nb+1][1], sB + off);
            }
            #pragma unroll
            for (int mf = 0; mf < 2; mf++)
                #pragma unroll
                for (int nf = 0; nf < 6; nf++)
                    mma_f16(acc[mf][nf], a[mf], b[nf]);
        }
        if (c < 15) { convA(xr, cur ^ 1); CPA_WAIT0(); }
        __syncthreads();
    }

    // epilogue: Q, K fp16 direct; V staged fp16 transposed ([64 d][80] pitch)
    __half* sVh = (__half*)smem;   // 64*80*2 = 10240 B
    #pragma unroll
    for (int mf = 0; mf < 2; mf++)
        #pragma unroll
        for (int nf = 0; nf < 6; nf++) {
            int gc = wn * 48 + nf * 8 + (lane & 3) * 2;
            int mt = gc >> 6, cm = gc & 63;
            int r0 = wm * 32 + mf * 16 + (lane >> 2);
            #pragma unroll
            for (int h = 0; h < 2; h++) {
                int rl = r0 + h * 8;
                float v0 = acc[mf][nf][h * 2 + 0], v1 = acc[mf][nf][h * 2 + 1];
                if (mt == 0) {
                    size_t o = (size_t)(row0 + rl) * DH + cm;
                    *(uint32_t*)(g_Q + o) = pk2(h16(v0 + bq[cm]), h16(v1 + bq[cm + 1]));
                } else if (mt == 1) {
                    size_t o = (size_t)(row0 + rl) * DH + cm;
                    *(uint32_t*)(g_K + o) = pk2(h16(v0 + bk[cm]), h16(v1 + bk[cm + 1]));
                } else {
                    sVh[cm * 80 + rl]       = __ushort_as_half(h16(v0 + bv[cm]));
                    sVh[(cm + 1) * 80 + rl] = __ushort_as_half(h16(v1 + bv[cm + 1]));
                }
            }
        }
    __syncthreads();
    // transposed V store: 64 d-rows x 64 i halves = 512 uint4
    #pragma unroll
    for (int p = 0; p < 2; p++) {
        int lin = p * 256 + tid, r = lin >> 3, q = lin & 7;
        *(uint4*)((char*)g_Vf + ((size_t)(bb * 64 + r) * SEQ + iloc) * 2 + q * 16) =
            *(uint4*)((char*)sVh + r * 160 + q * 16);
    }
}

// ---------------- scores -> E = exp(S) (fp16) + atomic column sums ----------------
// grid (16,16,8), block 256. smem: Q,K [128][72]h (36864 B); reused as Est fp16 pitch 136.
__global__ __launch_bounds__(256) void scores_kernel() {
    extern __shared__ char smem[];
    __shared__ float sred[256];
    const int tid = threadIdx.x, lane = tid & 31, w = tid >> 5;
    const int jt = blockIdx.x, it = blockIdx.y, bb = blockIdx.z;
    const int i0 = it * 128, j0 = jt * 128;
    const uint32_t sbase = s_u32(smem);

    {
        const __half* src[2] = { g_Q, g_K };
        #pragma unroll
        for (int a = 0; a < 2; a++) {
            const int rb = bb * SEQ + ((a == 0) ? i0 : j0);
            #pragma unroll
            for (int p = 0; p < 4; p++) {
                int lin = p * 256 + tid, r = lin >> 3, q = lin & 7;
                CPA16(sbase + a * 18432 + (uint32_t)(r * 144 + q * 16),
                      (const char*)src[a] + ((size_t)(rb + r) * DH) * 2 + q * 16);
            }
        }
        CPA_COMMIT(); CPA_WAIT0();
    }
    __syncthreads();

    const uint32_t sQ = sbase, sK = sbase + 18432;
    const int wm = w & 1, wn = w >> 1;          // rows wm*64, cols wn*32
    float acc[4][4][4];
    #pragma unroll
    for (int i = 0; i < 4; i++)
        #pragma unroll
        for (int j = 0; j < 4; j++)
            #pragma unroll
            for (int q = 0; q < 4; q++) acc[i][j][q] = 0.f;

    #pragma unroll
    for (int ks = 0; ks < 4; ks++) {
        const int k0 = ks * 16;
        uint32_t a[4][4];
        #pragma unroll
        for (int mf = 0; mf < 4; mf++) {
            uint32_t off = (uint32_t)((wm * 64 + mf * 16 + (lane & 15)) * 72 +
                                      k0 + ((lane >> 4) << 3)) * 2;
            LDSM4(a[mf][0], a[mf][1], a[mf][2], a[mf][3], sQ + off);
        }
        uint32_t b[4][2];
        #pragma unroll
        for (int nb = 0; nb < 2; nb++) {
            uint32_t off = (uint32_t)((wn * 32 + nb * 16 + (lane & 7) + ((lane >> 4) << 3)) * 72 +
                                      k0 + (((lane >> 3) & 1) << 3)) * 2;
            LDSM4(b[2*nb][0], b[2*nb][1], b[2*nb+1][0], b[2*nb+1][1], sK + off);
        }
        #pragma unroll
        for (int mf = 0; mf < 4; mf++)
            #pragma unroll
            for (int nf = 0; nf < 4; nf++)
                mma_f16(acc[mf][nf], a[mf], b[nf]);
    }
    __syncthreads();

    // stage E = exp(S/8) as fp16 (pitch 136 halves)
    __half* Est = (__half*)smem;
    #pragma unroll
    for (int mf = 0; mf < 4; mf++)
        #pragma unroll
        for (int nf = 0; nf < 4; nf++) {
            int col = wn * 32 + nf * 8 + (lane & 3) * 2;
            int r0 = wm * 64 + mf * 16 + (lane >> 2);
            #pragma unroll
            for (int h = 0; h < 2; h++) {
                float e0 = __expf(0.125f * acc[mf][nf][h * 2 + 0]);
                float e1 = __expf(0.125f * acc[mf][nf][h * 2 + 1]);
                *(__half2*)(Est + (r0 + h * 8) * 136 + col) = __floats2half2_rn(e0, e1);
            }
        }
    __syncthreads();
    // coalesced fp16 E store
    #pragma unroll
    for (int p = 0; p < 8; p++) {
        int lin = p * 256 + tid, r = lin >> 4, c8 = lin & 15;
        *(uint4*)((char*)g_E + ((size_t)(bb * SEQ + i0 + r) * SEQ + j0) * 2 + c8 * 16) =
            *(uint4*)((char*)Est + r * 272 + c8 * 16);
    }
    // per-column partial sums (2-way row split) + atomic accumulate
    {
        int col = tid & 127, hf = tid >> 7;
        float s = 0.f;
        #pragma unroll 8
        for (int i = 0; i < 64; i++) s += __half2float(Est[(hf * 64 + i) * 136 + col]);
        sred[tid] = s;
        __syncthreads();
        if (tid < 128)
            atomicAdd(&g_csum[bb * SEQ + j0 + tid], sred[tid] + sred[tid + 128]);
    }
}

// ---------------- output: 2-stage fp16 GEMM O = E @ (c*V), c applied in smem ----------------
// grid (32,8), block 128 (4 warps 2x2). C [64][64]; 16 j-chunks of 128.
// smem: 2 stages x 34816 (E 17408 + V 17408) + inv-csum table 4096 = 73728 -> 3 CTAs/SM
__global__ __launch_bounds__(128) void out_kernel(float* __restrict__ out) {
    extern __shared__ char smem[];
    const int tid = threadIdx.x, lane = tid & 31, w = tid >> 5;
    const int it = blockIdx.x, bb = blockIdx.y;
    const int i0 = it * 64;
    const uint32_t sbase = s_u32(smem);
    __half* ch = (__half*)(smem + 69632);   // 2048 inverse column sums

    const int wm = w & 1, wn = w >> 1;
    float acc[2][4][4];
    #pragma unroll
    for (int i = 0; i < 2; i++)
        #pragma unroll
        for (int j = 0; j < 4; j++)
            #pragma unroll
            for (int q = 0; q < 4; q++) acc[i][j][q] = 0.f;

    const char* Eg = (const char*)g_E;
    const char* Vg = (const char*)g_Vf;

    auto issue = [&](int c) {
        const uint32_t base = sbase + (c & 1) * 34816;
        const int j0 = c * 128;
        #pragma unroll
        for (int p = 0; p < 8; p++) {
            int lin = p * 128 + tid, r = lin >> 4, q = lin & 15;
            CPA16(base + (uint32_t)(r * 272 + q * 16),
                  Eg + ((size_t)(bb * SEQ + i0 + r) * SEQ + j0) * 2 + q * 16);
        }
        #pragma unroll
        for (int p = 0; p < 8; p++) {
            int lin = p * 128 + tid, r = lin >> 4, q = lin & 15;
            CPA16(base + 17408 + (uint32_t)(r * 272 + q * 16),
                  Vg + ((size_t)(bb * 64 + r) * SEQ + j0) * 2 + q * 16);
        }
        CPA_COMMIT();
    };

    issue(0);
    // build inverse-csum table (LDG latency overlaps the cp.asyncs above)
    #pragma unroll
    for (int p = 0; p < 16; p++) {
        int j = p * 128 + tid;
        ch[j] = __float2half(__fdividef(1.0f, g_csum[bb * SEQ + j]));
    }

    for (int c = 0; c < 16; c++) {
        if (c + 1 < 16) { issue(c + 1); CPA_WAIT1(); }
        else            { CPA_WAIT0(); }
        __syncthreads();   // also publishes ch on first iteration

        const uint32_t base = sbase + (c & 1) * 34816;
        // scale V tile in place: V[d][j] *= ch[j0 + j]
        {
            const __half2* cp2 = (const __half2*)(ch + c * 128 + (tid & 15) * 8);
            __half2 c0 = cp2[0], c1 = cp2[1], c2 = cp2[2], c3 = cp2[3];
            char* vb = smem + (c & 1) * 34816 + 17408;
            int g = tid & 15, rb = tid >> 4;
            #pragma unroll
            for (int p = 0; p < 8; p++) {
                uint4* vp = (uint4*)(vb + (rb + p * 8) * 272 + g * 16);
                uint4 v = *vp;
                __half2 h0 = __hmul2(*(__half2*)&v.x, c0);
                __half2 h1 = __hmul2(*(__half2*)&v.y, c1);
                __half2 h2 = __hmul2(*(__half2*)&v.z, c2);
                __half2 h3 = __hmul2(*(__half2*)&v.w, c3);
                v.x = *(uint32_t*)&h0; v.y = *(uint32_t*)&h1;
                v.z = *(uint32_t*)&h2; v.w = *(uint32_t*)&h3;
                *vp = v;
            }
        }
        __syncthreads();

        const uint32_t sE = base, sV = base + 17408;
        #pragma unroll
        for (int ks = 0; ks < 8; ks++) {
            const int k0 = ks * 16;
            uint32_t a[2][4];
            #pragma unroll
            for (int mf = 0; mf < 2; mf++) {
                uint32_t off = (uint32_t)((wm * 32 + mf * 16 + (lane & 15)) * 136 +
                                          k0 + ((lane >> 4) << 3)) * 2;
                LDSM4(a[mf][0], a[mf][1], a[mf][2], a[mf][3], sE + off);
            }
            uint32_t b[4][2];
            #pragma unroll
            for (int nb = 0; nb < 2; nb++) {
                uint32_t off = (uint32_t)((wn * 32 + nb * 16 + (lane & 7) + ((lane >> 4) << 3)) * 136 +
                                          k0 + (((lane >> 3) & 1) << 3)) * 2;
                LDSM4(b[2*nb][0], b[2*nb][1], b[2*nb+1][0], b[2*nb+1][1], sV + off);
            }
            #pragma unroll
            for (int mf = 0; mf < 2; mf++)
                #pragma unroll
                for (int nf = 0; nf < 4; nf++)
                    mma_f16(acc[mf][nf], a[mf], b[nf]);
        }
        __syncthreads();
    }

    // epilogue: stage f32 (pitch 68) then coalesced store
    float* Ost = (float*)smem;
    #pragma unroll
    for (int mf = 0; mf < 2; mf++)
        #pragma unroll
        for (int nf = 0; nf < 4; nf++) {
            int col = wn * 32 + nf * 8 + (lane & 3) * 2;
            int r0 = wm * 32 + mf * 16 + (lane >> 2);
            #pragma unroll
            for (int h = 0; h < 2; h++) {
                Ost[(r0 + h * 8) * 68 + col]     = acc[mf][nf][h * 2 + 0];
                Ost[(r0 + h * 8) * 68 + col + 1] = acc[mf][nf][h * 2 + 1];
            }
        }
    __syncthreads();
    #pragma unroll
    for (int p = 0; p < 8; p++) {
        int lin = p * 128 + tid, r = lin >> 4, c4 = lin & 15;
        *(float4*)(out + ((size_t)(bb * SEQ + i0 + r)) * DH + c4 * 4) =
            *(float4*)(Ost + r * 68 + c4 * 4);
    }
}

// ---------------- launch ----------------
extern "C" void kernel_launch(void* const* d_in, const int* in_sizes, int n_in,
                              void* d_out, int out_size)
{
    const float* x  = (const float*)d_in[0];
    const float* Wq = (const float*)d_in[1];
    const float* bq = (const float*)d_in[2];
    const float* Wk = (const float*)d_in[3];
    const float* bk = (const float*)d_in[4];
    const float* Wv = (const float*)d_in[5];
    const float* bv = (const float*)d_in[6];
    float* out = (float*)d_out;

    cudaFuncSetAttribute(proj_kernel,   cudaFuncAttributeMaxDynamicSharedMemorySize, 73728);
    cudaFuncSetAttribute(scores_kernel, cudaFuncAttributeMaxDynamicSharedMemorySize, 36864);
    cudaFuncSetAttribute(out_kernel,    cudaFuncAttributeMaxDynamicSharedMemorySize, 73728);

    split_w_kernel<<<dim3(256, 3), 256>>>(Wq, Wk, Wv);   // also zeroes g_csum
    proj_kernel<<<256, 256, 73728>>>(x, bq, bk, bv);
    scores_kernel<<<dim3(16, 16, 8), 256, 36864>>>();
    out_kernel<<<dim3(32, 8), 128, 73728>>>(out);
}